// round 7
// baseline (speedup 1.0000x reference)
#include <cuda_runtime.h>

// EM-routing capsule layer. B=64, S=14, I=32 -> N=6272/batch, C=10, D=16, 3 iters.
// Pass 0 linearized; passes 1-2 stream pose once each, 2 CTAs/SM.
// R7: software-pipelined softmax (overlaps next-s votes), transposed
//     conflict-free zz exchange, per-row pose consumption (lower reg pressure).

#define BB   64
#define SSQ  196
#define II   32
#define CCL  10
#define EPSf 1e-9f
#define L2E  1.4426950408889634f

typedef unsigned long long u64;

__device__ float g0[128 * 10 * 69 * 32];        // pass0 per-(cta,warp) slabs
__device__ float g_partial[256 * CCL * 34];     // per (b*4+sl, c): [0]=rsum [1..16]=sv [17..32]=sv2
__device__ float g_stats[BB * CCL * 34];        // per (b,c): [0..15]=nms [16..31]=siv [32]=cst (log2)

__device__ __forceinline__ u64 pack2(float lo, float hi) {
    u64 r; asm("mov.b64 %0,{%1,%2};" : "=l"(r) : "f"(lo), "f"(hi)); return r;
}
__device__ __forceinline__ void unpack2(u64 v, float& lo, float& hi) {
    asm("mov.b64 {%0,%1},%2;" : "=f"(lo), "=f"(hi) : "l"(v));
}
__device__ __forceinline__ u64 fma2(u64 a, u64 b, u64 c) {
    u64 d; asm("fma.rn.f32x2 %0,%1,%2,%3;" : "=l"(d) : "l"(a), "l"(b), "l"(c)); return d;
}
__device__ __forceinline__ u64 add2(u64 a, u64 b) {
    u64 d; asm("add.rn.f32x2 %0,%1,%2;" : "=l"(d) : "l"(a), "l"(b)); return d;
}
__device__ __forceinline__ u64 mul2(u64 a, u64 b) {
    u64 d; asm("mul.rn.f32x2 %0,%1,%2;" : "=l"(d) : "l"(a), "l"(b)); return d;
}
__device__ __forceinline__ float ex2f(float x) {
    float y; asm("ex2.approx.f32 %0,%1;" : "=f"(y) : "f"(x)); return y;
}

// ---------------- pass 0: linear/quadratic reduction over pose ----------------
__global__ __launch_bounds__(320, 1)
void pass0_kernel(const float* __restrict__ pose, const float* __restrict__ act)
{
    const int cta = blockIdx.x, b = cta >> 1, half = cta & 1;
    const int wpid = threadIdx.x >> 5, i = threadIdx.x & 31;

    float aP[16], G[40], X1[4], X2[4];
    float ra = 0.f, rc1 = 0.f, rc2 = 0.f, rq1 = 0.f, rq2 = 0.f;
    #pragma unroll
    for (int f = 0; f < 16; f++) aP[f] = 0.f;
    #pragma unroll
    for (int f = 0; f < 40; f++) G[f] = 0.f;
    #pragma unroll
    for (int f = 0; f < 4; f++) { X1[f] = 0.f; X2[f] = 0.f; }

    for (int sl = wpid; sl < 98; sl += 10) {
        const int s  = half * 98 + sl;
        const int h  = s / 14;
        const int wx = s - h * 14;
        const float cr = (h  + 0.5f) * (1.0f / 14.0f);
        const float cw = (wx + 0.5f) * (1.0f / 14.0f);

        const size_t nidx = ((size_t)(b * SSQ + s) * II + i);
        const float4* pv = reinterpret_cast<const float4*>(pose + nidx * 16);
        float p16[16];
        #pragma unroll
        for (int q4 = 0; q4 < 4; q4++) {
            float4 t = pv[q4];
            p16[q4*4+0] = t.x; p16[q4*4+1] = t.y; p16[q4*4+2] = t.z; p16[q4*4+3] = t.w;
        }
        const float a = act[nidx];

        #pragma unroll
        for (int p = 0; p < 4; p++) {
            float t0 = a * p16[p*4+0], t1 = a * p16[p*4+1];
            float t2 = a * p16[p*4+2], t3 = a * p16[p*4+3];
            aP[p*4+0] += t0; aP[p*4+1] += t1; aP[p*4+2] += t2; aP[p*4+3] += t3;
            float* Gp = G + p * 10;
            Gp[0] = fmaf(t0, p16[p*4+0], Gp[0]);
            Gp[1] = fmaf(t0, p16[p*4+1], Gp[1]);
            Gp[2] = fmaf(t0, p16[p*4+2], Gp[2]);
            Gp[3] = fmaf(t0, p16[p*4+3], Gp[3]);
            Gp[4] = fmaf(t1, p16[p*4+1], Gp[4]);
            Gp[5] = fmaf(t1, p16[p*4+2], Gp[5]);
            Gp[6] = fmaf(t1, p16[p*4+3], Gp[6]);
            Gp[7] = fmaf(t2, p16[p*4+2], Gp[7]);
            Gp[8] = fmaf(t2, p16[p*4+3], Gp[8]);
            Gp[9] = fmaf(t3, p16[p*4+3], Gp[9]);
        }
        ra += a;
        const float acr = a * cr, acw = a * cw;
        rc1 += acr; rc2 += acw;
        rq1 = fmaf(acr, cr, rq1); rq2 = fmaf(acw, cw, rq2);
        #pragma unroll
        for (int q = 0; q < 4; q++) {
            X1[q] = fmaf(acr, p16[q], X1[q]);
            X2[q] = fmaf(acw, p16[q], X2[q]);
        }
    }

    float* o = g0 + (size_t)(cta * 10 + wpid) * 69 * 32 + i;
    #pragma unroll
    for (int f = 0; f < 16; f++) o[f * 32] = aP[f];
    #pragma unroll
    for (int f = 0; f < 40; f++) o[(16 + f) * 32] = G[f];
    o[56 * 32] = ra;
    o[57 * 32] = rc1; o[58 * 32] = rc2;
    o[59 * 32] = rq1; o[60 * 32] = rq2;
    #pragma unroll
    for (int f = 0; f < 4; f++) { o[(61 + f) * 32] = X1[f]; o[(65 + f) * 32] = X2[f]; }
}

// ---------------- pass 0 stats ----------------
__global__ __launch_bounds__(320, 1)
void stats0_kernel(const float* __restrict__ wt,
                   const float* __restrict__ beta_v,
                   const float* __restrict__ beta_a)
{
    __shared__ float sm[32][72];
    const int b = blockIdx.x, tid = threadIdx.x;

    for (int t = tid; t < 32 * 69; t += 320) {
        const int i = t / 69, f = t - i * 69;
        float s = 0.f;
        #pragma unroll
        for (int k = 0; k < 20; k++) {
            const int cta = b * 2 + (k >= 10 ? 1 : 0);
            const int ww  = k - (k >= 10 ? 10 : 0);
            s += g0[(size_t)(cta * 10 + ww) * 69 * 32 + f * 32 + i];
        }
        sm[i][f] = s;
    }
    __syncthreads();

    if (tid < 160) {
        const int c = tid >> 4, d = tid & 15, p = d >> 2, r = d & 3;
        float RA = 0.f, RC = 0.f, RQ = 0.f, Sv = 0.f, Sv2 = 0.f, Cr = 0.f;
        for (int i = 0; i < 32; i++) {
            const float* g = sm[i];
            const float* wr = wt + (i * CCL + c) * 16;
            const float W0 = wr[0*4+r], W1 = wr[1*4+r], W2 = wr[2*4+r], W3 = wr[3*4+r];
            const float* ap = g + p * 4;
            Sv += ap[0]*W0 + ap[1]*W1 + ap[2]*W2 + ap[3]*W3;
            const float* Gp = g + 16 + p * 10;
            Sv2 += W0*W0*Gp[0] + W1*W1*Gp[4] + W2*W2*Gp[7] + W3*W3*Gp[9]
                 + 2.f*(W0*W1*Gp[1] + W0*W2*Gp[2] + W0*W3*Gp[3]
                      + W1*W2*Gp[5] + W1*W3*Gp[6] + W2*W3*Gp[8]);
            RA += g[56];
            if (d == 0) { RC += g[57]; RQ += g[59]; Cr += W0*g[61]+W1*g[62]+W2*g[63]+W3*g[64]; }
            else if (d == 1) { RC += g[58]; RQ += g[60]; Cr += W0*g[65]+W1*g[66]+W2*g[67]+W3*g[68]; }
        }
        float coordm = (d == 0 || d == 1) ? RC : 0.f;
        float coordv = (d == 0 || d == 1) ? (2.f * Cr + RQ) : 0.f;
        float mean = (Sv + coordm) / RA;
        float var  = fmaxf((Sv2 + coordv) / RA - mean * mean, 0.f);
        float lg   = __logf(sqrtf(var) + EPSf);
        float rr_sum = RA * 0.1f;
        float cost = (beta_v[c] + lg) * rr_sum, lgs = lg;
        #pragma unroll
        for (int off = 8; off; off >>= 1) {
            cost += __shfl_xor_sync(0xffffffffu, cost, off, 16);
            lgs  += __shfl_xor_sync(0xffffffffu, lgs,  off, 16);
        }
        float oact = 1.f / (1.f + __expf(-(beta_a[c] - cost)));   // invT = 1
        float siv  = sqrtf(L2E / (2.f * var + EPSf));
        float* st = g_stats + (b * CCL + c) * 34;
        st[d]      = -mean * siv;
        st[16 + d] = siv;
        if (d == 0) st[32] = (__logf(oact + EPSf) - lgs) * L2E;
    }
}

// ---------------- routing passes 1 and 2 (streaming, pipelined) ----------------

// compute stage for spatial index K (stores into V2/ZC/AC register bank)
#define COMPUTE(K, V2, ZC, AC) {                                               \
    const int _buf = (K) & 1;                                                  \
    float4 _pf; float _pa;                                                     \
    const bool _doPf = ((K) < 48);                                             \
    if (_doPf) {                                                               \
        const size_t _nbn = nb0 + (size_t)((K) + 1) * II;                      \
        if (tid < 128)      _pf = pose4[_nbn * 4 + tid];                       \
        else if (tid < 160) _pa = act[_nbn + (tid - 128)];                     \
    }                                                                          \
    const float2 _cc2 = s_coord[(K)];                                          \
    V2[0] = pack2(_cc2.x, _cc2.y);                                             \
    _Pragma("unroll")                                                          \
    for (int _j = 1; _j < 8; _j++) V2[_j] = 0ULL;                              \
    _Pragma("unroll")                                                          \
    for (int _p = 0; _p < 4; _p++) {                                           \
        float4 _tp = s_tile[_buf][sxp[_p]];                                    \
        u64 _pp;                                                               \
        _pp = pack2(_tp.x, _tp.x);                                             \
        V2[_p*2+0] = fma2(_pp, W2[0][0], V2[_p*2+0]);                          \
        V2[_p*2+1] = fma2(_pp, W2[0][1], V2[_p*2+1]);                          \
        _pp = pack2(_tp.y, _tp.y);                                             \
        V2[_p*2+0] = fma2(_pp, W2[1][0], V2[_p*2+0]);                          \
        V2[_p*2+1] = fma2(_pp, W2[1][1], V2[_p*2+1]);                          \
        _pp = pack2(_tp.z, _tp.z);                                             \
        V2[_p*2+0] = fma2(_pp, W2[2][0], V2[_p*2+0]);                          \
        V2[_p*2+1] = fma2(_pp, W2[2][1], V2[_p*2+1]);                          \
        _pp = pack2(_tp.w, _tp.w);                                             \
        V2[_p*2+0] = fma2(_pp, W2[3][0], V2[_p*2+0]);                          \
        V2[_p*2+1] = fma2(_pp, W2[3][1], V2[_p*2+1]);                          \
    }                                                                          \
    AC = s_act[_buf][lane];                                                    \
    u64 _az0 = 0ULL, _az1 = 0ULL;                                              \
    _Pragma("unroll")                                                          \
    for (int _j = 0; _j < 8; _j++) {                                           \
        u64 _nm, _sviv;                                                        \
        asm volatile("ld.shared.v2.b64 {%0,%1},[%2];"                          \
                     : "=l"(_nm), "=l"(_sviv) : "r"(stat_base + 16u * _j));    \
        u64 _t = fma2(V2[_j], _sviv, _nm);                                     \
        if (_j & 1) _az1 = fma2(_t, _t, _az1);                                 \
        else        _az0 = fma2(_t, _t, _az0);                                 \
    }                                                                          \
    { float _l0,_h0,_l1,_h1; unpack2(_az0,_l0,_h0); unpack2(_az1,_l1,_h1);     \
      ZC = cstc - ((_l0 + _l1) + (_h0 + _h1)); }                               \
    s_zz[_buf][czz + lane] = ZC;                                               \
    if (_doPf) {                                                               \
        if (tid < 128)      { const int _sx = tid ^ ((tid >> 3) & 7);          \
                              s_tile[_buf ^ 1][_sx] = _pf; }                   \
        else if (tid < 160) s_act[_buf ^ 1][tid - 128] = _pa;                  \
    }                                                                          \
}

// softmax + accumulate for spatial index K (consumes bank V2/ZC/AC)
#define FINISH(K, V2, ZC, AC) {                                                \
    const float* _zr = &s_zz[(K) & 1][lane];                                   \
    float _Z0 = 0.f, _Z1 = 0.f;                                                \
    _Pragma("unroll")                                                          \
    for (int _j = 0; _j < 10; _j++) {                                          \
        float _e = ex2f(_zr[_j * 32] - ZC);                                    \
        if (_j & 1) _Z1 += _e; else _Z0 += _e;                                 \
    }                                                                          \
    const float _rrp = __fdividef(AC, _Z0 + _Z1);                              \
    rsum += _rrp;                                                              \
    const u64 _rr2 = pack2(_rrp, _rrp);                                        \
    _Pragma("unroll")                                                          \
    for (int _j = 0; _j < 8; _j++) {                                           \
        const u64 _rv = mul2(_rr2, V2[_j]);                                    \
        sv[_j]  = add2(sv[_j], _rv);                                           \
        sv2[_j] = fma2(_rv, V2[_j], sv2[_j]);                                  \
    }                                                                          \
}

template<int IT>
__global__ __launch_bounds__(320, 2)
void accum_kernel(const float* __restrict__ pose,
                  const float* __restrict__ act,
                  const float* __restrict__ wt,
                  const float* __restrict__ beta_v,
                  const float* __restrict__ beta_a)
{
    __shared__ float4 s_tile[2][128];
    __shared__ float  s_act[2][32];
    __shared__ float  s_zz[2][320];                    // [buf][c*32 + i], conflict-free both ways
    __shared__ __align__(16) float s_stat[CCL][8][4];  // per pair j: nms0,nms1,siv0,siv1
    __shared__ float  s_cst[CCL];
    __shared__ float2 s_coord[49];

    const int cta = blockIdx.x, b = cta >> 2, sl = cta & 3;
    const int tid = threadIdx.x, c = tid >> 5, lane = tid & 31;
    const int s0 = sl * 49;
    const int czz = c * 32;

    // ---- stats into smem ----
    if (tid < 160) {
        const int cc = tid >> 4, d = tid & 15;
        float nmsv, sivv, cstv = 0.f;
        if (IT == 1) {
            const float* st = g_stats + (b * CCL + cc) * 34;
            nmsv = st[d]; sivv = st[16 + d];
            if (d == 0) cstv = st[32];
        } else {
            float rsum0 = 0.f, sva = 0.f, sv2a = 0.f;
            #pragma unroll
            for (int q = 0; q < 4; q++) {
                const float* p = g_partial + ((b * 4 + q) * CCL + cc) * 34;
                rsum0 += p[0]; sva += p[1 + d]; sv2a += p[17 + d];
            }
            float mean = sva / rsum0;
            float var  = fmaxf(sv2a / rsum0 - mean * mean, 0.f);
            float lg   = __logf(sqrtf(var) + EPSf);
            float cost = (beta_v[cc] + lg) * rsum0, lgs = lg;
            #pragma unroll
            for (int off = 8; off; off >>= 1) {
                cost += __shfl_xor_sync(0xffffffffu, cost, off, 16);
                lgs  += __shfl_xor_sync(0xffffffffu, lgs,  off, 16);
            }
            float oact = 1.f / (1.f + __expf(-2.0f * (beta_a[cc] - cost)));  // invT = 2
            sivv = sqrtf(L2E / (2.f * var + EPSf));
            nmsv = -mean * sivv;
            if (d == 0) cstv = (__logf(oact + EPSf) - lgs) * L2E;
        }
        s_stat[cc][d >> 1][d & 1]       = nmsv;
        s_stat[cc][d >> 1][2 + (d & 1)] = sivv;
        if (d == 0) s_cst[cc] = cstv;
    } else if (tid >= 256 && tid < 305) {
        const int s = s0 + (tid - 256);
        const int h = s / 14, wx = s - h * 14;
        s_coord[tid - 256] = make_float2((h + 0.5f) * (1.0f/14.0f), (wx + 0.5f) * (1.0f/14.0f));
    }
    __syncthreads();

    // W, r-paired: W2[q][rr] = (W[q][2rr], W[q][2rr+1])  (16 regs)
    u64 W2[4][2];
    {
        const float* wr = wt + (lane * CCL + c) * 16;
        #pragma unroll
        for (int q = 0; q < 4; q++) {
            W2[q][0] = pack2(wr[q*4+0], wr[q*4+1]);
            W2[q][1] = pack2(wr[q*4+2], wr[q*4+3]);
        }
    }
    const float cstc = s_cst[c];
    const unsigned stat_base = (unsigned)__cvta_generic_to_shared(&s_stat[c][0][0]);

    // loop-invariant swizzled pose indices
    int sxp[4];
    #pragma unroll
    for (int p = 0; p < 4; p++) {
        const int idx = lane * 4 + p;
        sxp[p] = idx ^ ((idx >> 3) & 7);
    }

    u64 sv[8], sv2[8];
    #pragma unroll
    for (int j = 0; j < 8; j++) { sv[j] = 0ULL; sv2[j] = 0ULL; }
    float rsum = 0.f;

    const float4* pose4 = reinterpret_cast<const float4*>(pose);
    const size_t nb0 = ((size_t)(b * SSQ) + s0) * II;

    // preload tile 0
    if (tid < 128)      { const int sx = tid ^ ((tid >> 3) & 7); s_tile[0][sx] = pose4[nb0 * 4 + tid]; }
    else if (tid < 160) { s_act[0][tid - 128] = act[nb0 + (tid - 128)]; }
    __syncthreads();

    // pipelined main loop: softmax/accum of s=k-1 overlaps votes of s=k
    u64 vA[8], vB[8];
    float zcA, zcB, aA, aB;

    COMPUTE(0, vA, zcA, aA);
    __syncthreads();

    for (int kk = 1; kk < 49; kk += 2) {
        COMPUTE(kk, vB, zcB, aB);
        FINISH(kk - 1, vA, zcA, aA);
        __syncthreads();
        COMPUTE(kk + 1, vA, zcA, aA);
        FINISH(kk, vB, zcB, aB);
        __syncthreads();
    }
    FINISH(48, vA, zcA, aA);

    // reduce over the 32 lanes (capsule i)
    #pragma unroll
    for (int off = 16; off; off >>= 1) {
        rsum += __shfl_xor_sync(0xffffffffu, rsum, off);
        #pragma unroll
        for (int j = 0; j < 8; j++) {
            sv[j]  = add2(sv[j],  __shfl_xor_sync(0xffffffffu, sv[j],  off));
            sv2[j] = add2(sv2[j], __shfl_xor_sync(0xffffffffu, sv2[j], off));
        }
    }
    if (lane == 0) {
        float* o = g_partial + (cta * CCL + c) * 34;
        o[0] = rsum;
        #pragma unroll
        for (int j = 0; j < 8; j++) {
            float lo, hi;
            unpack2(sv[j],  lo, hi); o[1  + 2*j] = lo; o[2  + 2*j] = hi;
            unpack2(sv2[j], lo, hi); o[17 + 2*j] = lo; o[18 + 2*j] = hi;
        }
    }
}

// ---------------- final output ----------------
__global__ __launch_bounds__(160)
void finalize_out(const float* __restrict__ beta_v,
                  const float* __restrict__ beta_a,
                  float* __restrict__ out)
{
    const int b = blockIdx.x;
    const int c = threadIdx.x >> 4;
    const int d = threadIdx.x & 15;

    float rsum = 0.f, sv = 0.f, sv2 = 0.f;
    #pragma unroll
    for (int q = 0; q < 4; q++) {
        const float* p = g_partial + ((b * 4 + q) * CCL + c) * 34;
        rsum += p[0]; sv += p[1 + d]; sv2 += p[17 + d];
    }
    float mean = sv / rsum;
    float var  = fmaxf(sv2 / rsum - mean * mean, 0.f);
    float lg   = __logf(sqrtf(var) + EPSf);
    float cost = (beta_v[c] + lg) * rsum;
    #pragma unroll
    for (int off = 8; off; off >>= 1)
        cost += __shfl_xor_sync(0xffffffffu, cost, off, 16);

    float oact = 1.f / (1.f + __expf(-3.0f * (beta_a[c] - cost)));   // invT = 3

    out[(b * CCL + c) * 16 + d] = mean;
    if (d == 0) out[BB * CCL * 16 + b * CCL + c] = oact;
}

extern "C" void kernel_launch(void* const* d_in, const int* in_sizes, int n_in,
                              void* d_out, int out_size)
{
    const float* pose = (const float*)d_in[0];
    const float* act  = (const float*)d_in[1];
    const float* w    = (const float*)d_in[2];
    const float* bv   = (const float*)d_in[3];
    const float* ba   = (const float*)d_in[4];
    float* out = (float*)d_out;

    pass0_kernel <<<128, 320>>>(pose, act);
    stats0_kernel<<<64, 320>>>(w, bv, ba);
    accum_kernel<1><<<256, 320>>>(pose, act, w, bv, ba);
    accum_kernel<2><<<256, 320>>>(pose, act, w, bv, ba);
    finalize_out <<<64, 160>>>(bv, ba, out);
}

// round 8
// speedup vs baseline: 1.3204x; 1.3204x over previous
#include <cuda_runtime.h>

// EM-routing capsule layer. B=64, S=14, I=32 -> N=6272/batch, C=10, D=16, 3 iters.
// Pass 0 linearized; passes 1-2 stream pose once each, 2 CTAs/SM.
// R8: single-bank skewed pipeline: region = [LDG prefetch; FINISH(k-1); COMPUTE(k);
//     STS prefetch; bar]. Softmax MUFU burst of s=k-1 overlaps vote FMA of s=k
//     across skewed warps without a second register bank (R7 spilled).
//     Transposed conflict-free zz, dual accumulation chains, row-wise pose.

#define BB   64
#define SSQ  196
#define II   32
#define CCL  10
#define EPSf 1e-9f
#define L2E  1.4426950408889634f

typedef unsigned long long u64;

__device__ float g0[128 * 10 * 69 * 32];        // pass0 per-(cta,warp) slabs
__device__ float g_partial[256 * CCL * 34];     // per (b*4+sl, c): [0]=rsum [1..16]=sv [17..32]=sv2
__device__ float g_stats[BB * CCL * 34];        // per (b,c): [0..15]=nms [16..31]=siv [32]=cst (log2)

__device__ __forceinline__ u64 pack2(float lo, float hi) {
    u64 r; asm("mov.b64 %0,{%1,%2};" : "=l"(r) : "f"(lo), "f"(hi)); return r;
}
__device__ __forceinline__ void unpack2(u64 v, float& lo, float& hi) {
    asm("mov.b64 {%0,%1},%2;" : "=f"(lo), "=f"(hi) : "l"(v));
}
__device__ __forceinline__ u64 fma2(u64 a, u64 b, u64 c) {
    u64 d; asm("fma.rn.f32x2 %0,%1,%2,%3;" : "=l"(d) : "l"(a), "l"(b), "l"(c)); return d;
}
__device__ __forceinline__ u64 add2(u64 a, u64 b) {
    u64 d; asm("add.rn.f32x2 %0,%1,%2;" : "=l"(d) : "l"(a), "l"(b)); return d;
}
__device__ __forceinline__ u64 mul2(u64 a, u64 b) {
    u64 d; asm("mul.rn.f32x2 %0,%1,%2;" : "=l"(d) : "l"(a), "l"(b)); return d;
}
__device__ __forceinline__ float ex2f(float x) {
    float y; asm("ex2.approx.f32 %0,%1;" : "=f"(y) : "f"(x)); return y;
}

// ---------------- pass 0: linear/quadratic reduction over pose ----------------
__global__ __launch_bounds__(320, 1)
void pass0_kernel(const float* __restrict__ pose, const float* __restrict__ act)
{
    const int cta = blockIdx.x, b = cta >> 1, half = cta & 1;
    const int wpid = threadIdx.x >> 5, i = threadIdx.x & 31;

    float aP[16], G[40], X1[4], X2[4];
    float ra = 0.f, rc1 = 0.f, rc2 = 0.f, rq1 = 0.f, rq2 = 0.f;
    #pragma unroll
    for (int f = 0; f < 16; f++) aP[f] = 0.f;
    #pragma unroll
    for (int f = 0; f < 40; f++) G[f] = 0.f;
    #pragma unroll
    for (int f = 0; f < 4; f++) { X1[f] = 0.f; X2[f] = 0.f; }

    for (int sl = wpid; sl < 98; sl += 10) {
        const int s  = half * 98 + sl;
        const int h  = s / 14;
        const int wx = s - h * 14;
        const float cr = (h  + 0.5f) * (1.0f / 14.0f);
        const float cw = (wx + 0.5f) * (1.0f / 14.0f);

        const size_t nidx = ((size_t)(b * SSQ + s) * II + i);
        const float4* pv = reinterpret_cast<const float4*>(pose + nidx * 16);
        float p16[16];
        #pragma unroll
        for (int q4 = 0; q4 < 4; q4++) {
            float4 t = pv[q4];
            p16[q4*4+0] = t.x; p16[q4*4+1] = t.y; p16[q4*4+2] = t.z; p16[q4*4+3] = t.w;
        }
        const float a = act[nidx];

        #pragma unroll
        for (int p = 0; p < 4; p++) {
            float t0 = a * p16[p*4+0], t1 = a * p16[p*4+1];
            float t2 = a * p16[p*4+2], t3 = a * p16[p*4+3];
            aP[p*4+0] += t0; aP[p*4+1] += t1; aP[p*4+2] += t2; aP[p*4+3] += t3;
            float* Gp = G + p * 10;
            Gp[0] = fmaf(t0, p16[p*4+0], Gp[0]);
            Gp[1] = fmaf(t0, p16[p*4+1], Gp[1]);
            Gp[2] = fmaf(t0, p16[p*4+2], Gp[2]);
            Gp[3] = fmaf(t0, p16[p*4+3], Gp[3]);
            Gp[4] = fmaf(t1, p16[p*4+1], Gp[4]);
            Gp[5] = fmaf(t1, p16[p*4+2], Gp[5]);
            Gp[6] = fmaf(t1, p16[p*4+3], Gp[6]);
            Gp[7] = fmaf(t2, p16[p*4+2], Gp[7]);
            Gp[8] = fmaf(t2, p16[p*4+3], Gp[8]);
            Gp[9] = fmaf(t3, p16[p*4+3], Gp[9]);
        }
        ra += a;
        const float acr = a * cr, acw = a * cw;
        rc1 += acr; rc2 += acw;
        rq1 = fmaf(acr, cr, rq1); rq2 = fmaf(acw, cw, rq2);
        #pragma unroll
        for (int q = 0; q < 4; q++) {
            X1[q] = fmaf(acr, p16[q], X1[q]);
            X2[q] = fmaf(acw, p16[q], X2[q]);
        }
    }

    float* o = g0 + (size_t)(cta * 10 + wpid) * 69 * 32 + i;
    #pragma unroll
    for (int f = 0; f < 16; f++) o[f * 32] = aP[f];
    #pragma unroll
    for (int f = 0; f < 40; f++) o[(16 + f) * 32] = G[f];
    o[56 * 32] = ra;
    o[57 * 32] = rc1; o[58 * 32] = rc2;
    o[59 * 32] = rq1; o[60 * 32] = rq2;
    #pragma unroll
    for (int f = 0; f < 4; f++) { o[(61 + f) * 32] = X1[f]; o[(65 + f) * 32] = X2[f]; }
}

// ---------------- pass 0 stats ----------------
__global__ __launch_bounds__(320, 1)
void stats0_kernel(const float* __restrict__ wt,
                   const float* __restrict__ beta_v,
                   const float* __restrict__ beta_a)
{
    __shared__ float sm[32][72];
    const int b = blockIdx.x, tid = threadIdx.x;

    for (int t = tid; t < 32 * 69; t += 320) {
        const int i = t / 69, f = t - i * 69;
        float s = 0.f;
        #pragma unroll
        for (int k = 0; k < 20; k++) {
            const int cta = b * 2 + (k >= 10 ? 1 : 0);
            const int ww  = k - (k >= 10 ? 10 : 0);
            s += g0[(size_t)(cta * 10 + ww) * 69 * 32 + f * 32 + i];
        }
        sm[i][f] = s;
    }
    __syncthreads();

    if (tid < 160) {
        const int c = tid >> 4, d = tid & 15, p = d >> 2, r = d & 3;
        float RA = 0.f, RC = 0.f, RQ = 0.f, Sv = 0.f, Sv2 = 0.f, Cr = 0.f;
        for (int i = 0; i < 32; i++) {
            const float* g = sm[i];
            const float* wr = wt + (i * CCL + c) * 16;
            const float W0 = wr[0*4+r], W1 = wr[1*4+r], W2 = wr[2*4+r], W3 = wr[3*4+r];
            const float* ap = g + p * 4;
            Sv += ap[0]*W0 + ap[1]*W1 + ap[2]*W2 + ap[3]*W3;
            const float* Gp = g + 16 + p * 10;
            Sv2 += W0*W0*Gp[0] + W1*W1*Gp[4] + W2*W2*Gp[7] + W3*W3*Gp[9]
                 + 2.f*(W0*W1*Gp[1] + W0*W2*Gp[2] + W0*W3*Gp[3]
                      + W1*W2*Gp[5] + W1*W3*Gp[6] + W2*W3*Gp[8]);
            RA += g[56];
            if (d == 0) { RC += g[57]; RQ += g[59]; Cr += W0*g[61]+W1*g[62]+W2*g[63]+W3*g[64]; }
            else if (d == 1) { RC += g[58]; RQ += g[60]; Cr += W0*g[65]+W1*g[66]+W2*g[67]+W3*g[68]; }
        }
        float coordm = (d == 0 || d == 1) ? RC : 0.f;
        float coordv = (d == 0 || d == 1) ? (2.f * Cr + RQ) : 0.f;
        float mean = (Sv + coordm) / RA;
        float var  = fmaxf((Sv2 + coordv) / RA - mean * mean, 0.f);
        float lg   = __logf(sqrtf(var) + EPSf);
        float rr_sum = RA * 0.1f;
        float cost = (beta_v[c] + lg) * rr_sum, lgs = lg;
        #pragma unroll
        for (int off = 8; off; off >>= 1) {
            cost += __shfl_xor_sync(0xffffffffu, cost, off, 16);
            lgs  += __shfl_xor_sync(0xffffffffu, lgs,  off, 16);
        }
        float oact = 1.f / (1.f + __expf(-(beta_a[c] - cost)));   // invT = 1
        float siv  = sqrtf(L2E / (2.f * var + EPSf));
        float* st = g_stats + (b * CCL + c) * 34;
        st[d]      = -mean * siv;
        st[16 + d] = siv;
        if (d == 0) st[32] = (__logf(oact + EPSf) - lgs) * L2E;
    }
}

// ---------------- routing passes 1 and 2 ----------------

// votes + zz for spatial index K; fills V2/ZC/AC; stores zz (pre-barrier)
#define COMPUTE_BODY(K, V2, ZC, AC) {                                          \
    const float2 _cc2 = s_coord[(K)];                                          \
    V2[0] = pack2(_cc2.x, _cc2.y);                                             \
    _Pragma("unroll")                                                          \
    for (int _j = 1; _j < 8; _j++) V2[_j] = 0ULL;                              \
    _Pragma("unroll")                                                          \
    for (int _p = 0; _p < 4; _p++) {                                           \
        float4 _tp = s_tile[(K) & 1][sxp[_p]];                                 \
        u64 _pp;                                                               \
        _pp = pack2(_tp.x, _tp.x);                                             \
        V2[_p*2+0] = fma2(_pp, W2[0][0], V2[_p*2+0]);                          \
        V2[_p*2+1] = fma2(_pp, W2[0][1], V2[_p*2+1]);                          \
        _pp = pack2(_tp.y, _tp.y);                                             \
        V2[_p*2+0] = fma2(_pp, W2[1][0], V2[_p*2+0]);                          \
        V2[_p*2+1] = fma2(_pp, W2[1][1], V2[_p*2+1]);                          \
        _pp = pack2(_tp.z, _tp.z);                                             \
        V2[_p*2+0] = fma2(_pp, W2[2][0], V2[_p*2+0]);                          \
        V2[_p*2+1] = fma2(_pp, W2[2][1], V2[_p*2+1]);                          \
        _pp = pack2(_tp.w, _tp.w);                                             \
        V2[_p*2+0] = fma2(_pp, W2[3][0], V2[_p*2+0]);                          \
        V2[_p*2+1] = fma2(_pp, W2[3][1], V2[_p*2+1]);                          \
    }                                                                          \
    AC = s_act[(K) & 1][lane];                                                 \
    u64 _az0 = 0ULL, _az1 = 0ULL;                                              \
    _Pragma("unroll")                                                          \
    for (int _j = 0; _j < 8; _j++) {                                           \
        u64 _nm, _sviv;                                                        \
        asm volatile("ld.shared.v2.b64 {%0,%1},[%2];"                          \
                     : "=l"(_nm), "=l"(_sviv) : "r"(stat_base + 16u * _j));    \
        u64 _t = fma2(V2[_j], _sviv, _nm);                                     \
        if (_j & 1) _az1 = fma2(_t, _t, _az1);                                 \
        else        _az0 = fma2(_t, _t, _az0);                                 \
    }                                                                          \
    { float _l0,_h0,_l1,_h1; unpack2(_az0,_l0,_h0); unpack2(_az1,_l1,_h1);     \
      ZC = cstc - ((_l0 + _l1) + (_h0 + _h1)); }                               \
    s_zz[(K) & 1][czz + lane] = ZC;                                            \
}

// softmax + accumulate for spatial index K (post-barrier; consumes V2/ZC/AC)
#define FINISH(K, V2, ZC, AC) {                                                \
    const float* _zr = &s_zz[(K) & 1][lane];                                   \
    float _Z0 = 0.f, _Z1 = 0.f;                                                \
    _Pragma("unroll")                                                          \
    for (int _j = 0; _j < 10; _j++) {                                          \
        float _e = ex2f(_zr[_j * 32] - ZC);                                    \
        if (_j & 1) _Z1 += _e; else _Z0 += _e;                                 \
    }                                                                          \
    const float _rrp = __fdividef(AC, _Z0 + _Z1);                              \
    rsum += _rrp;                                                              \
    const u64 _rr2 = pack2(_rrp, _rrp);                                        \
    _Pragma("unroll")                                                          \
    for (int _j = 0; _j < 8; _j++) {                                           \
        const u64 _rv = mul2(_rr2, V2[_j]);                                    \
        sv[_j]  = add2(sv[_j], _rv);                                           \
        sv2[_j] = fma2(_rv, V2[_j], sv2[_j]);                                  \
    }                                                                          \
}

template<int IT>
__global__ __launch_bounds__(320, 2)
void accum_kernel(const float* __restrict__ pose,
                  const float* __restrict__ act,
                  const float* __restrict__ wt,
                  const float* __restrict__ beta_v,
                  const float* __restrict__ beta_a)
{
    __shared__ float4 s_tile[2][128];
    __shared__ float  s_act[2][32];
    __shared__ float  s_zz[2][320];                    // [buf][c*32 + i], conflict-free
    __shared__ __align__(16) float s_stat[CCL][8][4];  // per pair j: nms0,nms1,siv0,siv1
    __shared__ float  s_cst[CCL];
    __shared__ float2 s_coord[49];

    const int cta = blockIdx.x, b = cta >> 2, sl = cta & 3;
    const int tid = threadIdx.x, c = tid >> 5, lane = tid & 31;
    const int s0 = sl * 49;
    const int czz = c * 32;

    // ---- stats into smem ----
    if (tid < 160) {
        const int cc = tid >> 4, d = tid & 15;
        float nmsv, sivv, cstv = 0.f;
        if (IT == 1) {
            const float* st = g_stats + (b * CCL + cc) * 34;
            nmsv = st[d]; sivv = st[16 + d];
            if (d == 0) cstv = st[32];
        } else {
            float rsum0 = 0.f, sva = 0.f, sv2a = 0.f;
            #pragma unroll
            for (int q = 0; q < 4; q++) {
                const float* p = g_partial + ((b * 4 + q) * CCL + cc) * 34;
                rsum0 += p[0]; sva += p[1 + d]; sv2a += p[17 + d];
            }
            float mean = sva / rsum0;
            float var  = fmaxf(sv2a / rsum0 - mean * mean, 0.f);
            float lg   = __logf(sqrtf(var) + EPSf);
            float cost = (beta_v[cc] + lg) * rsum0, lgs = lg;
            #pragma unroll
            for (int off = 8; off; off >>= 1) {
                cost += __shfl_xor_sync(0xffffffffu, cost, off, 16);
                lgs  += __shfl_xor_sync(0xffffffffu, lgs,  off, 16);
            }
            float oact = 1.f / (1.f + __expf(-2.0f * (beta_a[cc] - cost)));  // invT = 2
            sivv = sqrtf(L2E / (2.f * var + EPSf));
            nmsv = -mean * sivv;
            if (d == 0) cstv = (__logf(oact + EPSf) - lgs) * L2E;
        }
        s_stat[cc][d >> 1][d & 1]       = nmsv;
        s_stat[cc][d >> 1][2 + (d & 1)] = sivv;
        if (d == 0) s_cst[cc] = cstv;
    } else if (tid >= 256 && tid < 305) {
        const int s = s0 + (tid - 256);
        const int h = s / 14, wx = s - h * 14;
        s_coord[tid - 256] = make_float2((h + 0.5f) * (1.0f/14.0f), (wx + 0.5f) * (1.0f/14.0f));
    }
    __syncthreads();

    // W, r-paired: W2[q][rr] = (W[q][2rr], W[q][2rr+1])
    u64 W2[4][2];
    {
        const float* wr = wt + (lane * CCL + c) * 16;
        #pragma unroll
        for (int q = 0; q < 4; q++) {
            W2[q][0] = pack2(wr[q*4+0], wr[q*4+1]);
            W2[q][1] = pack2(wr[q*4+2], wr[q*4+3]);
        }
    }
    const float cstc = s_cst[c];
    const unsigned stat_base = (unsigned)__cvta_generic_to_shared(&s_stat[c][0][0]);

    int sxp[4];
    #pragma unroll
    for (int p = 0; p < 4; p++) {
        const int idx = lane * 4 + p;
        sxp[p] = idx ^ ((idx >> 3) & 7);
    }

    u64 sv[8], sv2[8];
    #pragma unroll
    for (int j = 0; j < 8; j++) { sv[j] = 0ULL; sv2[j] = 0ULL; }
    float rsum = 0.f;

    const float4* pose4 = reinterpret_cast<const float4*>(pose);
    const size_t nb0 = ((size_t)(b * SSQ) + s0) * II;

    // preload tile 0
    if (tid < 128)      { const int sx = tid ^ ((tid >> 3) & 7); s_tile[0][sx] = pose4[nb0 * 4 + tid]; }
    else if (tid < 160) { s_act[0][tid - 128] = act[nb0 + (tid - 128)]; }
    __syncthreads();

    u64 vA[8]; float zcA, aA;

    // region 0: compute s=0, prefetch s=1
    {
        float4 pf; float pa;
        const size_t nbn = nb0 + (size_t)II;
        if (tid < 128)      pf = pose4[nbn * 4 + tid];
        else if (tid < 160) pa = act[nbn + (tid - 128)];
        COMPUTE_BODY(0, vA, zcA, aA);
        if (tid < 128)      { const int sx = tid ^ ((tid >> 3) & 7); s_tile[1][sx] = pf; }
        else if (tid < 160) s_act[1][tid - 128] = pa;
    }
    __syncthreads();

    // regions 1..48: prefetch(k+1) | finish(k-1) | compute(k)
    for (int k = 1; k < 49; k++) {
        float4 pf; float pa;
        const bool doPf = (k < 48);
        if (doPf) {
            const size_t nbn = nb0 + (size_t)(k + 1) * II;
            if (tid < 128)      pf = pose4[nbn * 4 + tid];
            else if (tid < 160) pa = act[nbn + (tid - 128)];
        }

        FINISH(k - 1, vA, zcA, aA);
        COMPUTE_BODY(k, vA, zcA, aA);

        if (doPf) {
            if (tid < 128)      { const int sx = tid ^ ((tid >> 3) & 7); s_tile[(k + 1) & 1][sx] = pf; }
            else if (tid < 160) s_act[(k + 1) & 1][tid - 128] = pa;
        }
        __syncthreads();
    }
    FINISH(48, vA, zcA, aA);

    // reduce over the 32 lanes (capsule i)
    #pragma unroll
    for (int off = 16; off; off >>= 1) {
        rsum += __shfl_xor_sync(0xffffffffu, rsum, off);
        #pragma unroll
        for (int j = 0; j < 8; j++) {
            sv[j]  = add2(sv[j],  __shfl_xor_sync(0xffffffffu, sv[j],  off));
            sv2[j] = add2(sv2[j], __shfl_xor_sync(0xffffffffu, sv2[j], off));
        }
    }
    if (lane == 0) {
        float* o = g_partial + (cta * CCL + c) * 34;
        o[0] = rsum;
        #pragma unroll
        for (int j = 0; j < 8; j++) {
            float lo, hi;
            unpack2(sv[j],  lo, hi); o[1  + 2*j] = lo; o[2  + 2*j] = hi;
            unpack2(sv2[j], lo, hi); o[17 + 2*j] = lo; o[18 + 2*j] = hi;
        }
    }
}

// ---------------- final output ----------------
__global__ __launch_bounds__(160)
void finalize_out(const float* __restrict__ beta_v,
                  const float* __restrict__ beta_a,
                  float* __restrict__ out)
{
    const int b = blockIdx.x;
    const int c = threadIdx.x >> 4;
    const int d = threadIdx.x & 15;

    float rsum = 0.f, sv = 0.f, sv2 = 0.f;
    #pragma unroll
    for (int q = 0; q < 4; q++) {
        const float* p = g_partial + ((b * 4 + q) * CCL + c) * 34;
        rsum += p[0]; sv += p[1 + d]; sv2 += p[17 + d];
    }
    float mean = sv / rsum;
    float var  = fmaxf(sv2 / rsum - mean * mean, 0.f);
    float lg   = __logf(sqrtf(var) + EPSf);
    float cost = (beta_v[c] + lg) * rsum;
    #pragma unroll
    for (int off = 8; off; off >>= 1)
        cost += __shfl_xor_sync(0xffffffffu, cost, off, 16);

    float oact = 1.f / (1.f + __expf(-3.0f * (beta_a[c] - cost)));   // invT = 3

    out[(b * CCL + c) * 16 + d] = mean;
    if (d == 0) out[BB * CCL * 16 + b * CCL + c] = oact;
}

extern "C" void kernel_launch(void* const* d_in, const int* in_sizes, int n_in,
                              void* d_out, int out_size)
{
    const float* pose = (const float*)d_in[0];
    const float* act  = (const float*)d_in[1];
    const float* w    = (const float*)d_in[2];
    const float* bv   = (const float*)d_in[3];
    const float* ba   = (const float*)d_in[4];
    float* out = (float*)d_out;

    pass0_kernel <<<128, 320>>>(pose, act);
    stats0_kernel<<<64, 320>>>(w, bv, ba);
    accum_kernel<1><<<256, 320>>>(pose, act, w, bv, ba);
    accum_kernel<2><<<256, 320>>>(pose, act, w, bv, ba);
    finalize_out <<<64, 160>>>(bv, ba, out);
}

// round 9
// speedup vs baseline: 1.3605x; 1.0303x over previous
#include <cuda_runtime.h>

// EM-routing capsule layer. B=64, S=14, I=32 -> N=6272/batch, C=10, D=16, 3 iters.
// Pass 0 linearized; passes 1-2 stream pose once each, 2 CTAs/SM.
// R9: R8 skewed pipeline + prefetch spread across 9/10 warps at float2
//     granularity (balanced LDG scoreboard latency; coalesced 256B/warp).

#define BB   64
#define SSQ  196
#define II   32
#define CCL  10
#define EPSf 1e-9f
#define L2E  1.4426950408889634f

typedef unsigned long long u64;

__device__ float g0[128 * 10 * 69 * 32];        // pass0 per-(cta,warp) slabs
__device__ float g_partial[256 * CCL * 34];     // per (b*4+sl, c): [0]=rsum [1..16]=sv [17..32]=sv2
__device__ float g_stats[BB * CCL * 34];        // per (b,c): [0..15]=nms [16..31]=siv [32]=cst (log2)

__device__ __forceinline__ u64 pack2(float lo, float hi) {
    u64 r; asm("mov.b64 %0,{%1,%2};" : "=l"(r) : "f"(lo), "f"(hi)); return r;
}
__device__ __forceinline__ void unpack2(u64 v, float& lo, float& hi) {
    asm("mov.b64 {%0,%1},%2;" : "=f"(lo), "=f"(hi) : "l"(v));
}
__device__ __forceinline__ u64 fma2(u64 a, u64 b, u64 c) {
    u64 d; asm("fma.rn.f32x2 %0,%1,%2,%3;" : "=l"(d) : "l"(a), "l"(b), "l"(c)); return d;
}
__device__ __forceinline__ u64 add2(u64 a, u64 b) {
    u64 d; asm("add.rn.f32x2 %0,%1,%2;" : "=l"(d) : "l"(a), "l"(b)); return d;
}
__device__ __forceinline__ u64 mul2(u64 a, u64 b) {
    u64 d; asm("mul.rn.f32x2 %0,%1,%2;" : "=l"(d) : "l"(a), "l"(b)); return d;
}
__device__ __forceinline__ float ex2f(float x) {
    float y; asm("ex2.approx.f32 %0,%1;" : "=f"(y) : "f"(x)); return y;
}

// ---------------- pass 0: linear/quadratic reduction over pose ----------------
__global__ __launch_bounds__(320, 1)
void pass0_kernel(const float* __restrict__ pose, const float* __restrict__ act)
{
    const int cta = blockIdx.x, b = cta >> 1, half = cta & 1;
    const int wpid = threadIdx.x >> 5, i = threadIdx.x & 31;

    float aP[16], G[40], X1[4], X2[4];
    float ra = 0.f, rc1 = 0.f, rc2 = 0.f, rq1 = 0.f, rq2 = 0.f;
    #pragma unroll
    for (int f = 0; f < 16; f++) aP[f] = 0.f;
    #pragma unroll
    for (int f = 0; f < 40; f++) G[f] = 0.f;
    #pragma unroll
    for (int f = 0; f < 4; f++) { X1[f] = 0.f; X2[f] = 0.f; }

    for (int sl = wpid; sl < 98; sl += 10) {
        const int s  = half * 98 + sl;
        const int h  = s / 14;
        const int wx = s - h * 14;
        const float cr = (h  + 0.5f) * (1.0f / 14.0f);
        const float cw = (wx + 0.5f) * (1.0f / 14.0f);

        const size_t nidx = ((size_t)(b * SSQ + s) * II + i);
        const float4* pv = reinterpret_cast<const float4*>(pose + nidx * 16);
        float p16[16];
        #pragma unroll
        for (int q4 = 0; q4 < 4; q4++) {
            float4 t = pv[q4];
            p16[q4*4+0] = t.x; p16[q4*4+1] = t.y; p16[q4*4+2] = t.z; p16[q4*4+3] = t.w;
        }
        const float a = act[nidx];

        #pragma unroll
        for (int p = 0; p < 4; p++) {
            float t0 = a * p16[p*4+0], t1 = a * p16[p*4+1];
            float t2 = a * p16[p*4+2], t3 = a * p16[p*4+3];
            aP[p*4+0] += t0; aP[p*4+1] += t1; aP[p*4+2] += t2; aP[p*4+3] += t3;
            float* Gp = G + p * 10;
            Gp[0] = fmaf(t0, p16[p*4+0], Gp[0]);
            Gp[1] = fmaf(t0, p16[p*4+1], Gp[1]);
            Gp[2] = fmaf(t0, p16[p*4+2], Gp[2]);
            Gp[3] = fmaf(t0, p16[p*4+3], Gp[3]);
            Gp[4] = fmaf(t1, p16[p*4+1], Gp[4]);
            Gp[5] = fmaf(t1, p16[p*4+2], Gp[5]);
            Gp[6] = fmaf(t1, p16[p*4+3], Gp[6]);
            Gp[7] = fmaf(t2, p16[p*4+2], Gp[7]);
            Gp[8] = fmaf(t2, p16[p*4+3], Gp[8]);
            Gp[9] = fmaf(t3, p16[p*4+3], Gp[9]);
        }
        ra += a;
        const float acr = a * cr, acw = a * cw;
        rc1 += acr; rc2 += acw;
        rq1 = fmaf(acr, cr, rq1); rq2 = fmaf(acw, cw, rq2);
        #pragma unroll
        for (int q = 0; q < 4; q++) {
            X1[q] = fmaf(acr, p16[q], X1[q]);
            X2[q] = fmaf(acw, p16[q], X2[q]);
        }
    }

    float* o = g0 + (size_t)(cta * 10 + wpid) * 69 * 32 + i;
    #pragma unroll
    for (int f = 0; f < 16; f++) o[f * 32] = aP[f];
    #pragma unroll
    for (int f = 0; f < 40; f++) o[(16 + f) * 32] = G[f];
    o[56 * 32] = ra;
    o[57 * 32] = rc1; o[58 * 32] = rc2;
    o[59 * 32] = rq1; o[60 * 32] = rq2;
    #pragma unroll
    for (int f = 0; f < 4; f++) { o[(61 + f) * 32] = X1[f]; o[(65 + f) * 32] = X2[f]; }
}

// ---------------- pass 0 stats ----------------
__global__ __launch_bounds__(320, 1)
void stats0_kernel(const float* __restrict__ wt,
                   const float* __restrict__ beta_v,
                   const float* __restrict__ beta_a)
{
    __shared__ float sm[32][72];
    const int b = blockIdx.x, tid = threadIdx.x;

    for (int t = tid; t < 32 * 69; t += 320) {
        const int i = t / 69, f = t - i * 69;
        float s = 0.f;
        #pragma unroll
        for (int k = 0; k < 20; k++) {
            const int cta = b * 2 + (k >= 10 ? 1 : 0);
            const int ww  = k - (k >= 10 ? 10 : 0);
            s += g0[(size_t)(cta * 10 + ww) * 69 * 32 + f * 32 + i];
        }
        sm[i][f] = s;
    }
    __syncthreads();

    if (tid < 160) {
        const int c = tid >> 4, d = tid & 15, p = d >> 2, r = d & 3;
        float RA = 0.f, RC = 0.f, RQ = 0.f, Sv = 0.f, Sv2 = 0.f, Cr = 0.f;
        for (int i = 0; i < 32; i++) {
            const float* g = sm[i];
            const float* wr = wt + (i * CCL + c) * 16;
            const float W0 = wr[0*4+r], W1 = wr[1*4+r], W2 = wr[2*4+r], W3 = wr[3*4+r];
            const float* ap = g + p * 4;
            Sv += ap[0]*W0 + ap[1]*W1 + ap[2]*W2 + ap[3]*W3;
            const float* Gp = g + 16 + p * 10;
            Sv2 += W0*W0*Gp[0] + W1*W1*Gp[4] + W2*W2*Gp[7] + W3*W3*Gp[9]
                 + 2.f*(W0*W1*Gp[1] + W0*W2*Gp[2] + W0*W3*Gp[3]
                      + W1*W2*Gp[5] + W1*W3*Gp[6] + W2*W3*Gp[8]);
            RA += g[56];
            if (d == 0) { RC += g[57]; RQ += g[59]; Cr += W0*g[61]+W1*g[62]+W2*g[63]+W3*g[64]; }
            else if (d == 1) { RC += g[58]; RQ += g[60]; Cr += W0*g[65]+W1*g[66]+W2*g[67]+W3*g[68]; }
        }
        float coordm = (d == 0 || d == 1) ? RC : 0.f;
        float coordv = (d == 0 || d == 1) ? (2.f * Cr + RQ) : 0.f;
        float mean = (Sv + coordm) / RA;
        float var  = fmaxf((Sv2 + coordv) / RA - mean * mean, 0.f);
        float lg   = __logf(sqrtf(var) + EPSf);
        float rr_sum = RA * 0.1f;
        float cost = (beta_v[c] + lg) * rr_sum, lgs = lg;
        #pragma unroll
        for (int off = 8; off; off >>= 1) {
            cost += __shfl_xor_sync(0xffffffffu, cost, off, 16);
            lgs  += __shfl_xor_sync(0xffffffffu, lgs,  off, 16);
        }
        float oact = 1.f / (1.f + __expf(-(beta_a[c] - cost)));   // invT = 1
        float siv  = sqrtf(L2E / (2.f * var + EPSf));
        float* st = g_stats + (b * CCL + c) * 34;
        st[d]      = -mean * siv;
        st[16 + d] = siv;
        if (d == 0) st[32] = (__logf(oact + EPSf) - lgs) * L2E;
    }
}

// ---------------- routing passes 1 and 2 ----------------

// votes + zz for spatial index K; fills V2/ZC/AC; stores zz (pre-barrier)
#define COMPUTE_BODY(K, V2, ZC, AC) {                                          \
    const float2 _cc2 = s_coord[(K)];                                          \
    V2[0] = pack2(_cc2.x, _cc2.y);                                             \
    _Pragma("unroll")                                                          \
    for (int _j = 1; _j < 8; _j++) V2[_j] = 0ULL;                              \
    _Pragma("unroll")                                                          \
    for (int _p = 0; _p < 4; _p++) {                                           \
        float4 _tp = s_tile[(K) & 1][sxp[_p]];                                 \
        u64 _pp;                                                               \
        _pp = pack2(_tp.x, _tp.x);                                             \
        V2[_p*2+0] = fma2(_pp, W2[0][0], V2[_p*2+0]);                          \
        V2[_p*2+1] = fma2(_pp, W2[0][1], V2[_p*2+1]);                          \
        _pp = pack2(_tp.y, _tp.y);                                             \
        V2[_p*2+0] = fma2(_pp, W2[1][0], V2[_p*2+0]);                          \
        V2[_p*2+1] = fma2(_pp, W2[1][1], V2[_p*2+1]);                          \
        _pp = pack2(_tp.z, _tp.z);                                             \
        V2[_p*2+0] = fma2(_pp, W2[2][0], V2[_p*2+0]);                          \
        V2[_p*2+1] = fma2(_pp, W2[2][1], V2[_p*2+1]);                          \
        _pp = pack2(_tp.w, _tp.w);                                             \
        V2[_p*2+0] = fma2(_pp, W2[3][0], V2[_p*2+0]);                          \
        V2[_p*2+1] = fma2(_pp, W2[3][1], V2[_p*2+1]);                          \
    }                                                                          \
    AC = s_act[(K) & 1][lane];                                                 \
    u64 _az0 = 0ULL, _az1 = 0ULL;                                              \
    _Pragma("unroll")                                                          \
    for (int _j = 0; _j < 8; _j++) {                                           \
        u64 _nm, _sviv;                                                        \
        asm volatile("ld.shared.v2.b64 {%0,%1},[%2];"                          \
                     : "=l"(_nm), "=l"(_sviv) : "r"(stat_base + 16u * _j));    \
        u64 _t = fma2(V2[_j], _sviv, _nm);                                     \
        if (_j & 1) _az1 = fma2(_t, _t, _az1);                                 \
        else        _az0 = fma2(_t, _t, _az0);                                 \
    }                                                                          \
    { float _l0,_h0,_l1,_h1; unpack2(_az0,_l0,_h0); unpack2(_az1,_l1,_h1);     \
      ZC = cstc - ((_l0 + _l1) + (_h0 + _h1)); }                               \
    s_zz[(K) & 1][czz + lane] = ZC;                                            \
}

// softmax + accumulate for spatial index K (consumes V2/ZC/AC)
#define FINISH(K, V2, ZC, AC) {                                                \
    const float* _zr = &s_zz[(K) & 1][lane];                                   \
    float _Z0 = 0.f, _Z1 = 0.f;                                                \
    _Pragma("unroll")                                                          \
    for (int _j = 0; _j < 10; _j++) {                                          \
        float _e = ex2f(_zr[_j * 32] - ZC);                                    \
        if (_j & 1) _Z1 += _e; else _Z0 += _e;                                 \
    }                                                                          \
    const float _rrp = __fdividef(AC, _Z0 + _Z1);                              \
    rsum += _rrp;                                                              \
    const u64 _rr2 = pack2(_rrp, _rrp);                                        \
    _Pragma("unroll")                                                          \
    for (int _j = 0; _j < 8; _j++) {                                           \
        const u64 _rv = mul2(_rr2, V2[_j]);                                    \
        sv[_j]  = add2(sv[_j], _rv);                                           \
        sv2[_j] = fma2(_rv, V2[_j], sv2[_j]);                                  \
    }                                                                          \
}

template<int IT>
__global__ __launch_bounds__(320, 2)
void accum_kernel(const float* __restrict__ pose,
                  const float* __restrict__ act,
                  const float* __restrict__ wt,
                  const float* __restrict__ beta_v,
                  const float* __restrict__ beta_a)
{
    __shared__ float4 s_tile[2][128];
    __shared__ float  s_act[2][32];
    __shared__ float  s_zz[2][320];                    // [buf][c*32 + i], conflict-free
    __shared__ __align__(16) float s_stat[CCL][8][4];  // per pair j: nms0,nms1,siv0,siv1
    __shared__ float  s_cst[CCL];
    __shared__ float2 s_coord[49];

    const int cta = blockIdx.x, b = cta >> 2, sl = cta & 3;
    const int tid = threadIdx.x, c = tid >> 5, lane = tid & 31;
    const int s0 = sl * 49;
    const int czz = c * 32;

    // ---- stats into smem ----
    if (tid < 160) {
        const int cc = tid >> 4, d = tid & 15;
        float nmsv, sivv, cstv = 0.f;
        if (IT == 1) {
            const float* st = g_stats + (b * CCL + cc) * 34;
            nmsv = st[d]; sivv = st[16 + d];
            if (d == 0) cstv = st[32];
        } else {
            float rsum0 = 0.f, sva = 0.f, sv2a = 0.f;
            #pragma unroll
            for (int q = 0; q < 4; q++) {
                const float* p = g_partial + ((b * 4 + q) * CCL + cc) * 34;
                rsum0 += p[0]; sva += p[1 + d]; sv2a += p[17 + d];
            }
            float mean = sva / rsum0;
            float var  = fmaxf(sv2a / rsum0 - mean * mean, 0.f);
            float lg   = __logf(sqrtf(var) + EPSf);
            float cost = (beta_v[cc] + lg) * rsum0, lgs = lg;
            #pragma unroll
            for (int off = 8; off; off >>= 1) {
                cost += __shfl_xor_sync(0xffffffffu, cost, off, 16);
                lgs  += __shfl_xor_sync(0xffffffffu, lgs,  off, 16);
            }
            float oact = 1.f / (1.f + __expf(-2.0f * (beta_a[cc] - cost)));  // invT = 2
            sivv = sqrtf(L2E / (2.f * var + EPSf));
            nmsv = -mean * sivv;
            if (d == 0) cstv = (__logf(oact + EPSf) - lgs) * L2E;
        }
        s_stat[cc][d >> 1][d & 1]       = nmsv;
        s_stat[cc][d >> 1][2 + (d & 1)] = sivv;
        if (d == 0) s_cst[cc] = cstv;
    } else if (tid >= 256 && tid < 305) {
        const int s = s0 + (tid - 256);
        const int h = s / 14, wx = s - h * 14;
        s_coord[tid - 256] = make_float2((h + 0.5f) * (1.0f/14.0f), (wx + 0.5f) * (1.0f/14.0f));
    }
    __syncthreads();

    // W, r-paired
    u64 W2[4][2];
    {
        const float* wr = wt + (lane * CCL + c) * 16;
        #pragma unroll
        for (int q = 0; q < 4; q++) {
            W2[q][0] = pack2(wr[q*4+0], wr[q*4+1]);
            W2[q][1] = pack2(wr[q*4+2], wr[q*4+3]);
        }
    }
    const float cstc = s_cst[c];
    const unsigned stat_base = (unsigned)__cvta_generic_to_shared(&s_stat[c][0][0]);

    // loop-invariant swizzled read indices (float4 granularity)
    int sxp[4];
    #pragma unroll
    for (int p = 0; p < 4; p++) {
        const int idx = lane * 4 + p;
        sxp[p] = idx ^ ((idx >> 3) & 7);
    }
    // loop-invariant swizzled STS index (float2 granularity): tid<256 stores float2 #tid
    const int idx4w = tid >> 1;
    const int sx2w  = (idx4w ^ ((idx4w >> 3) & 7)) * 2 + (tid & 1);

    u64 sv[8], sv2[8];
    #pragma unroll
    for (int j = 0; j < 8; j++) { sv[j] = 0ULL; sv2[j] = 0ULL; }
    float rsum = 0.f;

    const float2* pose2 = reinterpret_cast<const float2*>(pose);
    const size_t nb0 = ((size_t)(b * SSQ) + s0) * II;

    // preload tile 0 (float2 spread: warps 0-7 pose, warp 8 act)
    {
        float2* tile2 = reinterpret_cast<float2*>(&s_tile[0][0]);
        if (tid < 256)      tile2[sx2w] = pose2[nb0 * 8 + tid];
        else if (tid < 288) s_act[0][tid - 256] = act[nb0 + (tid - 256)];
    }
    __syncthreads();

    u64 vA[8]; float zcA, aA;

    // region 0: compute s=0, prefetch s=1
    {
        float2 pf; float pa;
        const size_t nbn = nb0 + (size_t)II;
        if (tid < 256)      pf = pose2[nbn * 8 + tid];
        else if (tid < 288) pa = act[nbn + (tid - 256)];
        COMPUTE_BODY(0, vA, zcA, aA);
        float2* tile2 = reinterpret_cast<float2*>(&s_tile[1][0]);
        if (tid < 256)      tile2[sx2w] = pf;
        else if (tid < 288) s_act[1][tid - 256] = pa;
    }
    __syncthreads();

    // regions 1..48: prefetch(k+1) | finish(k-1) | compute(k)
    for (int k = 1; k < 49; k++) {
        float2 pf; float pa;
        const bool doPf = (k < 48);
        if (doPf) {
            const size_t nbn = nb0 + (size_t)(k + 1) * II;
            if (tid < 256)      pf = pose2[nbn * 8 + tid];
            else if (tid < 288) pa = act[nbn + (tid - 256)];
        }

        FINISH(k - 1, vA, zcA, aA);
        COMPUTE_BODY(k, vA, zcA, aA);

        if (doPf) {
            float2* tile2 = reinterpret_cast<float2*>(&s_tile[(k + 1) & 1][0]);
            if (tid < 256)      tile2[sx2w] = pf;
            else if (tid < 288) s_act[(k + 1) & 1][tid - 256] = pa;
        }
        __syncthreads();
    }
    FINISH(48, vA, zcA, aA);

    // reduce over the 32 lanes (capsule i)
    #pragma unroll
    for (int off = 16; off; off >>= 1) {
        rsum += __shfl_xor_sync(0xffffffffu, rsum, off);
        #pragma unroll
        for (int j = 0; j < 8; j++) {
            sv[j]  = add2(sv[j],  __shfl_xor_sync(0xffffffffu, sv[j],  off));
            sv2[j] = add2(sv2[j], __shfl_xor_sync(0xffffffffu, sv2[j], off));
        }
    }
    if (lane == 0) {
        float* o = g_partial + (cta * CCL + c) * 34;
        o[0] = rsum;
        #pragma unroll
        for (int j = 0; j < 8; j++) {
            float lo, hi;
            unpack2(sv[j],  lo, hi); o[1  + 2*j] = lo; o[2  + 2*j] = hi;
            unpack2(sv2[j], lo, hi); o[17 + 2*j] = lo; o[18 + 2*j] = hi;
        }
    }
}

// ---------------- final output ----------------
__global__ __launch_bounds__(160)
void finalize_out(const float* __restrict__ beta_v,
                  const float* __restrict__ beta_a,
                  float* __restrict__ out)
{
    const int b = blockIdx.x;
    const int c = threadIdx.x >> 4;
    const int d = threadIdx.x & 15;

    float rsum = 0.f, sv = 0.f, sv2 = 0.f;
    #pragma unroll
    for (int q = 0; q < 4; q++) {
        const float* p = g_partial + ((b * 4 + q) * CCL + c) * 34;
        rsum += p[0]; sv += p[1 + d]; sv2 += p[17 + d];
    }
    float mean = sv / rsum;
    float var  = fmaxf(sv2 / rsum - mean * mean, 0.f);
    float lg   = __logf(sqrtf(var) + EPSf);
    float cost = (beta_v[c] + lg) * rsum;
    #pragma unroll
    for (int off = 8; off; off >>= 1)
        cost += __shfl_xor_sync(0xffffffffu, cost, off, 16);

    float oact = 1.f / (1.f + __expf(-3.0f * (beta_a[c] - cost)));   // invT = 3

    out[(b * CCL + c) * 16 + d] = mean;
    if (d == 0) out[BB * CCL * 16 + b * CCL + c] = oact;
}

extern "C" void kernel_launch(void* const* d_in, const int* in_sizes, int n_in,
                              void* d_out, int out_size)
{
    const float* pose = (const float*)d_in[0];
    const float* act  = (const float*)d_in[1];
    const float* w    = (const float*)d_in[2];
    const float* bv   = (const float*)d_in[3];
    const float* ba   = (const float*)d_in[4];
    float* out = (float*)d_out;

    pass0_kernel <<<128, 320>>>(pose, act);
    stats0_kernel<<<64, 320>>>(w, bv, ba);
    accum_kernel<1><<<256, 320>>>(pose, act, w, bv, ba);
    accum_kernel<2><<<256, 320>>>(pose, act, w, bv, ba);
    finalize_out <<<64, 160>>>(bv, ba, out);
}